// round 9
// baseline (speedup 1.0000x reference)
#include <cuda_runtime.h>
#include <cuda_fp16.h>
#include <math.h>
#include <stdint.h>

#define BB 128
#define MM 64
#define DD 512
#define KK 4096
#define CC 64
#define SSTRIDE 68

// ---------------------------------------------------------------------------
// scratch (__device__ globals per allocation-free rule)
// ---------------------------------------------------------------------------
__device__ __align__(16) __half g_Fh[BB*MM*DD];   // normalized feats, f16
__device__ __align__(16) __half g_Ch[KK*DD];      // C, f16, class-sorted rows
__device__ int     g_rank[KK];
__device__ uint8_t g_clsSorted[KK];
__device__ float   g_evi[BB*MM*CC];
__device__ float   g_w[BB*MM];
__device__ float   g_lp[BB*MM];

// ---------------------------------------------------------------------------
__device__ __forceinline__ uint32_t smem_to_u32(const void* p) {
    uint32_t a;
    asm("{ .reg .u64 t; cvta.to.shared.u64 t, %1; cvt.u32.u64 %0, t; }" : "=r"(a) : "l"(p));
    return a;
}
__device__ __forceinline__ void cp16(uint32_t dst, const void* src) {
    asm volatile("cp.async.cg.shared.global [%0], [%1], 16;" :: "r"(dst), "l"(src));
}
__device__ __forceinline__ void cp_commit() { asm volatile("cp.async.commit_group;" ::: "memory"); }
__device__ __forceinline__ void cp_wait0()  { asm volatile("cp.async.wait_group 0;" ::: "memory"); }
__device__ __forceinline__ void cp_wait1()  { asm volatile("cp.async.wait_group 1;" ::: "memory"); }

__device__ __forceinline__ void ldm_x4(uint32_t r[4], uint32_t addr) {
    asm volatile("ldmatrix.sync.aligned.m8n8.x4.shared.b16 {%0,%1,%2,%3}, [%4];"
        : "=r"(r[0]), "=r"(r[1]), "=r"(r[2]), "=r"(r[3]) : "r"(addr));
}
__device__ __forceinline__ void mma16816(float* c, const uint32_t* a, uint32_t b0, uint32_t b1) {
    asm volatile(
        "mma.sync.aligned.m16n8k16.row.col.f32.f16.f16.f32 "
        "{%0,%1,%2,%3}, {%4,%5,%6,%7}, {%8,%9}, {%0,%1,%2,%3};"
        : "+f"(c[0]), "+f"(c[1]), "+f"(c[2]), "+f"(c[3])
        : "r"(a[0]), "r"(a[1]), "r"(a[2]), "r"(a[3]), "r"(b0), "r"(b1));
}

// ---------------------------------------------------------------------------
// k_perm: deterministic stable class-sort ranks (grid 16, block 256)
// ---------------------------------------------------------------------------
__global__ void k_perm(const int* __restrict__ Ccls) {
    __shared__ int cls_s[KK];
    int tid = threadIdx.x;
    for (int i = tid; i < KK; i += 256) cls_s[i] = Ccls[i] & 63;
    __syncthreads();
    int i = blockIdx.x * 256 + tid;
    int ci = cls_s[i];
    int rank = 0;
    for (int j = 0; j < KK; j++) {
        int cj = cls_s[j];
        rank += (cj < ci) || (cj == ci && j < i);
    }
    g_rank[i] = rank;
    g_clsSorted[rank] = (uint8_t)ci;
}

// prep_C: fp32 -> f16, scatter rows to class-sorted positions
__global__ void prep_C(const float* __restrict__ Cmat) {
    long i = (long)blockIdx.x * 256 + threadIdx.x;      // over float4s
    int row = (int)(i >> 7), col4 = (int)(i & 127);
    float4 v = ((const float4*)Cmat)[i];
    int r = g_rank[row];
    __half2 h0 = __floats2half2_rn(v.x, v.y);
    __half2 h1 = __floats2half2_rn(v.z, v.w);
    uint2 u; u.x = *(uint32_t*)&h0; u.y = *(uint32_t*)&h1;
    ((uint2*)(g_Ch + (size_t)r * DD))[col4] = u;
}

// prep_F: l2-normalize rows of feats, f16. One warp per row.
__global__ void prep_F(const float* __restrict__ feats) {
    int row = blockIdx.x * 8 + (threadIdx.x >> 5);
    int lane = threadIdx.x & 31;
    const float4* rp = (const float4*)(feats + (size_t)row * DD);
    float4 v[4]; float ss = 0.f;
    #pragma unroll
    for (int u = 0; u < 4; u++) {
        v[u] = rp[lane + u*32];
        ss += v[u].x*v[u].x + v[u].y*v[u].y + v[u].z*v[u].z + v[u].w*v[u].w;
    }
    #pragma unroll
    for (int o = 16; o > 0; o >>= 1) ss += __shfl_xor_sync(0xffffffffu, ss, o);
    float inv = 1.0f / fmaxf(sqrtf(ss), 1e-12f);
    #pragma unroll
    for (int u = 0; u < 4; u++) {
        __half2 h0 = __floats2half2_rn(v[u].x*inv, v[u].y*inv);
        __half2 h1 = __floats2half2_rn(v[u].z*inv, v[u].w*inv);
        uint2 w; w.x = *(uint32_t*)&h0; w.y = *(uint32_t*)&h1;
        ((uint2*)(g_Fh + (size_t)row * DD))[lane + u*32] = w;
    }
}

// ---------------------------------------------------------------------------
// K1: soft-topk weights + log(P_sup)
// ---------------------------------------------------------------------------
__global__ void k_weights(const float* __restrict__ slot_prob,
                          const float* __restrict__ slot_mask) {
    int b = blockIdx.x, m = threadIdx.x;
    __shared__ float sv[MM];
    __shared__ float red[MM];
    __shared__ int   topi[3];
    __shared__ float s_mean, s_zmax, s_zsum, s_wsum, s_tmax, s_tsum;

    float mask = slot_mask[m];
    float pv = slot_prob[b*MM + m] * mask;
    sv[m] = pv;
    __syncthreads();
    if (m == 0) {
        for (int t = 0; t < 3; t++) {
            float best = -INFINITY; int bi = 0;
            for (int i = 0; i < MM; i++) if (sv[i] > best) { best = sv[i]; bi = i; }
            topi[t] = bi; sv[bi] = -INFINITY;
        }
    }
    __syncthreads();
    float keep = (m == topi[0] || m == topi[1] || m == topi[2]) ? 1.f : 0.f;
    float q = pv * keep;
    red[m] = q; __syncthreads();
    if (m == 0) { float s = 0.f; for (int i = 0; i < MM; i++) s += red[i]; s_mean = s / (float)MM; }
    __syncthreads();
    float z = (q - s_mean) * 2.0f;
    red[m] = z; __syncthreads();
    if (m == 0) { float mx = -INFINITY; for (int i = 0; i < MM; i++) mx = fmaxf(mx, red[i]); s_zmax = mx; }
    __syncthreads();
    float e = expf(z - s_zmax);
    red[m] = e; __syncthreads();
    if (m == 0) { float s = 0.f; for (int i = 0; i < MM; i++) s += red[i]; s_zsum = s; }
    __syncthreads();
    float w = (e / s_zsum) * mask;
    red[m] = w; __syncthreads();
    if (m == 0) { float s = 0.f; for (int i = 0; i < MM; i++) s += red[i]; s_wsum = s; }
    __syncthreads();
    w = w / fmaxf(s_wsum, 1e-8f);
    g_w[b*MM + m] = w;

    float t = logf(w + 1e-8f) * (1.0f/1.6f);
    red[m] = t; __syncthreads();
    if (m == 0) { float mx = -INFINITY; for (int i = 0; i < MM; i++) mx = fmaxf(mx, red[i]); s_tmax = mx; }
    __syncthreads();
    float et = expf(t - s_tmax);
    red[m] = et; __syncthreads();
    if (m == 0) { float s = 0.f; for (int i = 0; i < MM; i++) s += red[i]; s_tsum = s; }
    __syncthreads();
    float lp = t - s_tmax - logf(s_tsum);
    g_lp[b*MM + m] = fmaxf(lp, -18.420680744f);
}

// ---------------------------------------------------------------------------
// K2: f16 HMMA GEMM + in-register class exp-sum. 256 threads.
// CTA = (batch-pair bp = bx>>1, proto-half = bx&1).
// A (128x512 f16, 2 batches) resident; B: 2048 protos streamed as 8 tiles
// of 256 protos x 8 chunks of 64 k, 2-stage cp.async double buffer.
// Warps 2(m) x 4(n); warp tile 64m x 64n (= one sorted class per warp slab).
// ---------------------------------------------------------------------------
#define THREADS 256
#define ASTR_B  1040u       // A row stride bytes (520 f16)
#define BSTR_B  144u        // B row stride bytes (72 f16)
#define OFF_A   0u          // 128 rows x 1040 B = 133120
#define OFF_B   133120u
#define B_BUF   36864u      // 256 rows x 144 B
#define OFF_PART 206848u    // [128][5] f32 = 2560
#define OFF_CLS  209408u    // [4096] u8
#define SMEM_EVI 213504

// chunk q: nt = q>>3 (256-proto tile), dc = q&7 (64-k chunk)
// 256 rows x 8 groups = 2048 cp16 ops = 8 iterations x 256 threads (exact).
__device__ __forceinline__ void load_Bchunk(uint32_t base, int half, int q, int tid) {
    const int nt = q >> 3, dc = q & 7;
    const __half* src0 = g_Ch + (size_t)(half*2048 + nt*256)*DD + dc*64;
    #pragma unroll
    for (int ii = 0; ii < 8; ii++) {
        int i = tid + ii*THREADS;
        int n = i >> 3, g = i & 7;
        cp16(base + (uint32_t)n*BSTR_B + (uint32_t)g*16, src0 + (size_t)n*DD + g*8);
    }
}

__global__ void __launch_bounds__(THREADS, 1)
k_evi() {
    extern __shared__ __align__(1024) char smem[];
    uint32_t smem_base = smem_to_u32(smem);
    const int tid = threadIdx.x, wid = tid >> 5, lane = tid & 31;
    const int bp = blockIdx.x >> 1, half = blockIdx.x & 1;
    const int wr = wid & 1, wc = wid >> 1;     // 2 row-groups x 4 col-groups

    float*   part  = (float*)(smem + OFF_PART);   // [128][5]
    uint8_t* cls_s = (uint8_t*)(smem + OFF_CLS);

    // cls bytes (4096 B)
    cp16(smem_base + OFF_CLS + (uint32_t)tid*16, g_clsSorted + tid*16);

    // resident A (128 x 512 f16, stride 520) — batches 2bp, 2bp+1
    #pragma unroll
    for (int ii = 0; ii < 32; ii++) {
        int i = tid + ii*THREADS;
        int r = i >> 6, g = i & 63;
        const __half* src = g_Fh + ((size_t)(bp*2)*MM + r)*DD + g*8;
        cp16(smem_base + OFF_A + (uint32_t)r*ASTR_B + (uint32_t)g*16, src);
    }
    load_Bchunk(smem_base + OFF_B, half, 0, tid);
    cp_commit();

    const uint32_t aBase = smem_base + OFF_A
        + (uint32_t)(wr*64 + (lane & 15))*ASTR_B + (uint32_t)(lane >> 4)*16;
    const uint32_t bLane = (uint32_t)((lane & 7) + ((lane >> 4) << 3))*BSTR_B
        + (uint32_t)((lane >> 3) & 1)*16;

    float acc[4][8][4];

    for (int q = 0; q < 64; ++q) {
        const int nt = q >> 3, dc = q & 7;

        __syncthreads();   // all warps done with the buffer being overwritten
        if (q + 1 < 64) {
            load_Bchunk(smem_base + OFF_B + (uint32_t)((q+1) & 1)*B_BUF, half, q + 1, tid);
            cp_commit();
            cp_wait1();    // q's buffer complete
        } else {
            cp_wait0();
        }
        __syncthreads();   // q's data visible to all warps

        if (dc == 0) {
            #pragma unroll
            for (int i = 0; i < 4; i++)
                #pragma unroll
                for (int j = 0; j < 8; j++)
                    #pragma unroll
                    for (int v = 0; v < 4; v++) acc[i][j][v] = 0.f;
        }

        const uint32_t bBuf = smem_base + OFF_B + (uint32_t)(q & 1)*B_BUF
                            + (uint32_t)(wc*64)*BSTR_B + bLane;
        #pragma unroll
        for (int ks = 0; ks < 4; ++ks) {
            uint32_t a[4][4];
            uint32_t kb = (uint32_t)(dc*64 + ks*16)*2;
            ldm_x4(a[0], aBase + kb);
            ldm_x4(a[1], aBase + 16*ASTR_B + kb);
            ldm_x4(a[2], aBase + 32*ASTR_B + kb);
            ldm_x4(a[3], aBase + 48*ASTR_B + kb);
            uint32_t bf[4][4];
            uint32_t bAddr = bBuf + (uint32_t)ks*32;
            ldm_x4(bf[0], bAddr);
            ldm_x4(bf[1], bAddr + 16*BSTR_B);
            ldm_x4(bf[2], bAddr + 32*BSTR_B);
            ldm_x4(bf[3], bAddr + 48*BSTR_B);
            #pragma unroll
            for (int i = 0; i < 4; i++) {
                #pragma unroll
                for (int jj = 0; jj < 4; jj++) {
                    mma16816(acc[i][2*jj],   a[i], bf[jj][0], bf[jj][1]);
                    mma16816(acc[i][2*jj+1], a[i], bf[jj][2], bf[jj][3]);
                }
            }
        }

        if (dc == 7) {
            // in-register exp + row reduce over this warp's 64 cols (one class)
            #pragma unroll
            for (int i = 0; i < 4; i++) {
                #pragma unroll
                for (int h = 0; h < 2; h++) {
                    float s = 0.f;
                    #pragma unroll
                    for (int j = 0; j < 8; j++) {
                        s += __expf(2.0f * acc[i][j][h*2 + 0]);
                        s += __expf(2.0f * acc[i][j][h*2 + 1]);
                    }
                    s += __shfl_xor_sync(0xffffffffu, s, 1);
                    s += __shfl_xor_sync(0xffffffffu, s, 2);
                    if ((lane & 3) == 0) {
                        int row = wr*64 + i*16 + h*8 + (lane >> 2);
                        part[row*5 + wc] = s;
                    }
                }
            }
            __syncthreads();
            if (tid < 128) {
                int batch = bp*2 + (tid >> 6), slot = tid & 63;
                float* dst = g_evi + ((size_t)batch*MM + slot)*CC;
                #pragma unroll
                for (int j = 0; j < 4; ++j) {
                    int c = (int)cls_s[half*2048 + nt*256 + j*64];
                    dst[c] = 0.5f * logf(fmaxf(part[tid*5 + j], 1e-8f));
                }
            }
        }
    }
}

// ---------------------------------------------------------------------------
// K3: epilogue per batch (top1, cosines vs top1 slots, support LSE)
// ---------------------------------------------------------------------------
__global__ void __launch_bounds__(256, 1)
k_out(const float* __restrict__ S_slots,
      const float* __restrict__ alpha,
      float* __restrict__ out) {
    extern __shared__ float sm[];
    float* s_s   = sm;                        // [512][68]
    float* tf_s  = s_s  + DD*SSTRIDE;         // [256][68]; reused as sup_s
    float* evi_s = tf_s + 256*SSTRIDE;        // [64*64]
    float* w_s   = evi_s + MM*CC;
    float* lp_s  = w_s + MM;
    float* t1v   = lp_s + MM;
    int*   t1i   = (int*)(t1v + MM);

    int b = blockIdx.x, tid = threadIdx.x;
    int wid = tid >> 5, lane = tid & 31;

    for (int i = tid; i < MM*CC; i += 256) evi_s[i] = g_evi[(size_t)b*MM*CC + i];
    if (tid < MM) { w_s[tid] = g_w[b*MM + tid]; lp_s[tid] = g_lp[b*MM + tid]; }

    const float* sb = S_slots + (size_t)b*MM*DD;
    for (int rr = 0; rr < 8; rr++) {
        int r = wid*8 + rr;
        const float4* rp = (const float4*)(sb + r*DD);
        float4 v[4]; float ss = 0.f;
        #pragma unroll
        for (int u = 0; u < 4; u++) {
            v[u] = rp[u*32 + lane];
            ss += v[u].x*v[u].x + v[u].y*v[u].y + v[u].z*v[u].z + v[u].w*v[u].w;
        }
        #pragma unroll
        for (int o = 16; o > 0; o >>= 1) ss += __shfl_xor_sync(0xffffffffu, ss, o);
        float inv = 1.0f / fmaxf(sqrtf(ss), 1e-12f);
        #pragma unroll
        for (int u = 0; u < 4; u++) {
            int d0 = u*128 + lane*4;
            s_s[(d0+0)*SSTRIDE + r] = v[u].x * inv;
            s_s[(d0+1)*SSTRIDE + r] = v[u].y * inv;
            s_s[(d0+2)*SSTRIDE + r] = v[u].z * inv;
            s_s[(d0+3)*SSTRIDE + r] = v[u].w * inv;
        }
    }
    __syncthreads();

    if (tid < CC) {
        int c = tid;
        float best = -INFINITY; int bi = 0;
        for (int m = 0; m < MM; m++) {
            float sc = evi_s[m*CC + c] * w_s[m];
            if (sc > best) { best = sc; bi = m; }
        }
        t1v[c] = best; t1i[c] = bi;
    }
    __syncthreads();

    int tr = tid >> 4, tc = tid & 15;
    int gc = tid >> 2, gq = tid & 3;
    float acc[4][4] = {};
    #pragma unroll 1
    for (int h = 0; h < 2; h++) {
        __syncthreads();
        {
            int src = t1i[gc];
            for (int u = 0; u < 64; u++) {
                int k = gq*64 + u;
                tf_s[k*SSTRIDE + gc] = s_s[(h*256 + k)*SSTRIDE + src];
            }
        }
        __syncthreads();
        const float* fp = s_s  + h*256*SSTRIDE + tr*4;
        const float* gp = tf_s + tc*4;
        #pragma unroll 4
        for (int k = 0; k < 256; k++) {
            float4 fv = *(const float4*)(fp + k*SSTRIDE);
            float4 gv = *(const float4*)(gp + k*SSTRIDE);
            acc[0][0] = fmaf(fv.x, gv.x, acc[0][0]);
            acc[0][1] = fmaf(fv.x, gv.y, acc[0][1]);
            acc[0][2] = fmaf(fv.x, gv.z, acc[0][2]);
            acc[0][3] = fmaf(fv.x, gv.w, acc[0][3]);
            acc[1][0] = fmaf(fv.y, gv.x, acc[1][0]);
            acc[1][1] = fmaf(fv.y, gv.y, acc[1][1]);
            acc[1][2] = fmaf(fv.y, gv.z, acc[1][2]);
            acc[1][3] = fmaf(fv.y, gv.w, acc[1][3]);
            acc[2][0] = fmaf(fv.z, gv.x, acc[2][0]);
            acc[2][1] = fmaf(fv.z, gv.y, acc[2][1]);
            acc[2][2] = fmaf(fv.z, gv.z, acc[2][2]);
            acc[2][3] = fmaf(fv.z, gv.w, acc[2][3]);
            acc[3][0] = fmaf(fv.w, gv.x, acc[3][0]);
            acc[3][1] = fmaf(fv.w, gv.y, acc[3][1]);
            acc[3][2] = fmaf(fv.w, gv.z, acc[3][2]);
            acc[3][3] = fmaf(fv.w, gv.w, acc[3][3]);
        }
    }
    __syncthreads();
    float* sup_s = tf_s;
    #pragma unroll
    for (int i = 0; i < 4; i++) {
        #pragma unroll
        for (int j = 0; j < 4; j++) {
            int m = tr*4 + i, c = tc*4 + j;
            float cosv = fmaxf(acc[i][j], 0.f);
            float sr = evi_s[m*CC + c] + lp_s[m] - cosv;
            if (m == t1i[c]) sr = -10000.0f;
            sup_s[m*CC + c] = sr;
        }
    }
    __syncthreads();
    if (tid < CC) {
        int c = tid;
        float mx = -INFINITY;
        for (int m = 0; m < MM; m++) mx = fmaxf(mx, sup_s[m*CC + c]);
        float sum = 0.f;
        for (int m = 0; m < MM; m++) sum += expf(sup_s[m*CC + c] - mx);
        float sval = mx + logf(sum);
        out[b*CC + c] = alpha[0] * (t1v[c] + 0.4f * sval);
    }
}

// ---------------------------------------------------------------------------
extern "C" void kernel_launch(void* const* d_in, const int* in_sizes, int n_in,
                              void* d_out, int out_size) {
    const float* feats     = (const float*)d_in[0];
    const float* slot_prob = (const float*)d_in[1];
    const float* slot_mask = (const float*)d_in[2];
    const float* S_slots   = (const float*)d_in[3];
    const float* Cmat      = (const float*)d_in[4];
    const int*   Ccls      = (const int*)d_in[5];
    const float* alpha     = (const float*)d_in[6];
    float* out = (float*)d_out;

    const int smem3 = (DD*SSTRIDE + 256*SSTRIDE + MM*CC + 3*MM) * 4 + MM * 4;

    cudaFuncSetAttribute(k_evi, cudaFuncAttributeMaxDynamicSharedMemorySize, SMEM_EVI);
    cudaFuncSetAttribute(k_out, cudaFuncAttributeMaxDynamicSharedMemorySize, smem3);

    k_weights<<<BB, MM>>>(slot_prob, slot_mask);
    k_perm<<<KK/256, 256>>>(Ccls);
    prep_C<<<KK*DD/1024, 256>>>(Cmat);
    prep_F<<<BB*MM/8, 256>>>(feats);
    k_evi<<<BB, THREADS, SMEM_EVI>>>();
    k_out<<<BB, 256, smem3>>>(S_slots, alpha, out);
}

// round 10
// speedup vs baseline: 1.1239x; 1.1239x over previous
#include <cuda_runtime.h>
#include <cuda_fp16.h>
#include <math.h>
#include <stdint.h>

#define BB 128
#define MM 64
#define DD 512
#define KK 4096
#define CC 64

// ---------------------------------------------------------------------------
// scratch (__device__ globals per allocation-free rule)
// ---------------------------------------------------------------------------
__device__ __align__(16) __half g_Ch[KK*DD];      // C, f16, class-sorted rows
__device__ int     g_rank[KK];
__device__ uint8_t g_clsSorted[KK];
__device__ float   g_evi[BB*MM*CC];
__device__ float   g_w[BB*MM];
__device__ float   g_lp[BB*MM];

// ---------------------------------------------------------------------------
__device__ __forceinline__ uint32_t smem_to_u32(const void* p) {
    uint32_t a;
    asm("{ .reg .u64 t; cvta.to.shared.u64 t, %1; cvt.u32.u64 %0, t; }" : "=r"(a) : "l"(p));
    return a;
}
__device__ __forceinline__ void cp16(uint32_t dst, const void* src) {
    asm volatile("cp.async.cg.shared.global [%0], [%1], 16;" :: "r"(dst), "l"(src));
}
__device__ __forceinline__ void cp_commit() { asm volatile("cp.async.commit_group;" ::: "memory"); }
__device__ __forceinline__ void cp_wait0()  { asm volatile("cp.async.wait_group 0;" ::: "memory"); }
__device__ __forceinline__ void cp_wait1()  { asm volatile("cp.async.wait_group 1;" ::: "memory"); }

__device__ __forceinline__ void ldm_x4(uint32_t r[4], uint32_t addr) {
    asm volatile("ldmatrix.sync.aligned.m8n8.x4.shared.b16 {%0,%1,%2,%3}, [%4];"
        : "=r"(r[0]), "=r"(r[1]), "=r"(r[2]), "=r"(r[3]) : "r"(addr));
}
__device__ __forceinline__ void mma16816(float* c, const uint32_t* a, uint32_t b0, uint32_t b1) {
    asm volatile(
        "mma.sync.aligned.m16n8k16.row.col.f32.f16.f16.f32 "
        "{%0,%1,%2,%3}, {%4,%5,%6,%7}, {%8,%9}, {%0,%1,%2,%3};"
        : "+f"(c[0]), "+f"(c[1]), "+f"(c[2]), "+f"(c[3])
        : "r"(a[0]), "r"(a[1]), "r"(a[2]), "r"(a[3]), "r"(b0), "r"(b1));
}

// ---------------------------------------------------------------------------
// k_perm: deterministic stable class-sort ranks (grid 16, block 256)
// ---------------------------------------------------------------------------
__global__ void k_perm(const int* __restrict__ Ccls) {
    __shared__ int cls_s[KK];
    int tid = threadIdx.x;
    for (int i = tid; i < KK; i += 256) cls_s[i] = Ccls[i] & 63;
    __syncthreads();
    int i = blockIdx.x * 256 + tid;
    int ci = cls_s[i];
    int rank = 0;
    for (int j = 0; j < KK; j++) {
        int cj = cls_s[j];
        rank += (cj < ci) || (cj == ci && j < i);
    }
    g_rank[i] = rank;
    g_clsSorted[rank] = (uint8_t)ci;
}

// prep_C: fp32 -> f16, scatter rows to class-sorted positions
__global__ void prep_C(const float* __restrict__ Cmat) {
    long i = (long)blockIdx.x * 256 + threadIdx.x;      // over float4s
    int row = (int)(i >> 7), col4 = (int)(i & 127);
    float4 v = ((const float4*)Cmat)[i];
    int r = g_rank[row];
    __half2 h0 = __floats2half2_rn(v.x, v.y);
    __half2 h1 = __floats2half2_rn(v.z, v.w);
    uint2 u; u.x = *(uint32_t*)&h0; u.y = *(uint32_t*)&h1;
    ((uint2*)(g_Ch + (size_t)r * DD))[col4] = u;
}

// ---------------------------------------------------------------------------
// K1: soft-topk weights + log(P_sup)
// ---------------------------------------------------------------------------
__global__ void k_weights(const float* __restrict__ slot_prob,
                          const float* __restrict__ slot_mask) {
    int b = blockIdx.x, m = threadIdx.x;
    __shared__ float sv[MM];
    __shared__ float red[MM];
    __shared__ int   topi[3];
    __shared__ float s_mean, s_zmax, s_zsum, s_wsum, s_tmax, s_tsum;

    float mask = slot_mask[m];
    float pv = slot_prob[b*MM + m] * mask;
    sv[m] = pv;
    __syncthreads();
    if (m == 0) {
        for (int t = 0; t < 3; t++) {
            float best = -INFINITY; int bi = 0;
            for (int i = 0; i < MM; i++) if (sv[i] > best) { best = sv[i]; bi = i; }
            topi[t] = bi; sv[bi] = -INFINITY;
        }
    }
    __syncthreads();
    float keep = (m == topi[0] || m == topi[1] || m == topi[2]) ? 1.f : 0.f;
    float q = pv * keep;
    red[m] = q; __syncthreads();
    if (m == 0) { float s = 0.f; for (int i = 0; i < MM; i++) s += red[i]; s_mean = s / (float)MM; }
    __syncthreads();
    float z = (q - s_mean) * 2.0f;
    red[m] = z; __syncthreads();
    if (m == 0) { float mx = -INFINITY; for (int i = 0; i < MM; i++) mx = fmaxf(mx, red[i]); s_zmax = mx; }
    __syncthreads();
    float e = expf(z - s_zmax);
    red[m] = e; __syncthreads();
    if (m == 0) { float s = 0.f; for (int i = 0; i < MM; i++) s += red[i]; s_zsum = s; }
    __syncthreads();
    float w = (e / s_zsum) * mask;
    red[m] = w; __syncthreads();
    if (m == 0) { float s = 0.f; for (int i = 0; i < MM; i++) s += red[i]; s_wsum = s; }
    __syncthreads();
    w = w / fmaxf(s_wsum, 1e-8f);
    g_w[b*MM + m] = w;

    float t = logf(w + 1e-8f) * (1.0f/1.6f);
    red[m] = t; __syncthreads();
    if (m == 0) { float mx = -INFINITY; for (int i = 0; i < MM; i++) mx = fmaxf(mx, red[i]); s_tmax = mx; }
    __syncthreads();
    float et = expf(t - s_tmax);
    red[m] = et; __syncthreads();
    if (m == 0) { float s = 0.f; for (int i = 0; i < MM; i++) s += red[i]; s_tsum = s; }
    __syncthreads();
    float lp = t - s_tmax - logf(s_tsum);
    g_lp[b*MM + m] = fmaxf(lp, -18.420680744f);
}

// ---------------------------------------------------------------------------
// K2: f16 HMMA GEMM + in-register class exp-sum. 128 threads, 2 CTAs/SM.
// CTA = (batch b = bx>>1, proto-half = bx&1).
// A (64x512 f16, normalized in-kernel from fp32 feats) resident;
// B: 2048 protos streamed as 16 tiles of 128 protos x 8 chunks of 64 k,
// 2-stage cp.async double buffer.
// Warps 2(m) x 2(n); warp tile 32m x 64n (= one sorted class per warp slab).
// ---------------------------------------------------------------------------
#define THREADS 128
#define ASTR_B  1040u       // A row stride bytes (520 f16)
#define BSTR_B  144u        // B row stride bytes (72 f16)
#define OFF_A   0u          // 64 rows x 1040 B = 66560
#define OFF_B   66560u      // 2 x 18432
#define B_BUF   18432u      // 128 rows x 144 B
#define OFF_PART 103424u    // [64][2] f32 = 512
#define SMEM_EVI 103936

// chunk q: nt = q>>3 (128-proto tile), dc = q&7 (64-k chunk)
// 128 rows x 8 groups = 1024 cp16 = 8 iterations x 128 threads (exact)
__device__ __forceinline__ void load_Bchunk(uint32_t base, int half, int q, int tid) {
    const int nt = q >> 3, dc = q & 7;
    const __half* src0 = g_Ch + (size_t)(half*2048 + nt*128)*DD + dc*64;
    #pragma unroll
    for (int ii = 0; ii < 8; ii++) {
        int i = tid + ii*THREADS;
        int n = i >> 3, g = i & 7;
        cp16(base + (uint32_t)n*BSTR_B + (uint32_t)g*16, src0 + (size_t)n*DD + g*8);
    }
}

__global__ void __launch_bounds__(THREADS, 2)
k_evi(const float* __restrict__ feats) {
    extern __shared__ __align__(1024) char smem[];
    uint32_t smem_base = smem_to_u32(smem);
    const int tid = threadIdx.x, wid = tid >> 5, lane = tid & 31;
    const int b = blockIdx.x >> 1, half = blockIdx.x & 1;
    const int wr = wid & 1, wc = wid >> 1;     // 2 row-groups x 2 col-groups

    float* part = (float*)(smem + OFF_PART);   // [64][2]

    // start B chunk 0 early
    load_Bchunk(smem_base + OFF_B, half, 0, tid);
    cp_commit();

    // A fill: normalize 64 rows of feats (fp32) -> f16 smem, stride 520
    {
        const float* fb = feats + (size_t)b*MM*DD;
        for (int rr = 0; rr < 16; rr++) {
            int row = wid*16 + rr;
            const float4* rp = (const float4*)(fb + (size_t)row*DD);
            float4 v[4]; float ss = 0.f;
            #pragma unroll
            for (int u = 0; u < 4; u++) {
                v[u] = rp[lane + u*32];
                ss += v[u].x*v[u].x + v[u].y*v[u].y + v[u].z*v[u].z + v[u].w*v[u].w;
            }
            #pragma unroll
            for (int o = 16; o > 0; o >>= 1) ss += __shfl_xor_sync(0xffffffffu, ss, o);
            float inv = 1.0f / fmaxf(sqrtf(ss), 1e-12f);
            #pragma unroll
            for (int u = 0; u < 4; u++) {
                __half2 h0 = __floats2half2_rn(v[u].x*inv, v[u].y*inv);
                __half2 h1 = __floats2half2_rn(v[u].z*inv, v[u].w*inv);
                uint2 w; w.x = *(uint32_t*)&h0; w.y = *(uint32_t*)&h1;
                *(uint2*)(smem + OFF_A + (uint32_t)row*ASTR_B + (uint32_t)(lane + u*32)*8) = w;
            }
        }
    }

    const uint32_t aBase = smem_base + OFF_A
        + (uint32_t)(wr*32 + (lane & 15))*ASTR_B + (uint32_t)(lane >> 4)*16;
    const uint32_t bLane = (uint32_t)((lane & 7) + ((lane >> 4) << 3))*BSTR_B
        + (uint32_t)((lane >> 3) & 1)*16;

    float acc[2][8][4];

    for (int q = 0; q < 128; ++q) {
        const int nt = q >> 3, dc = q & 7;

        __syncthreads();   // A visible (q=0); prior q's buffer free; part consumed
        if (q + 1 < 128) {
            load_Bchunk(smem_base + OFF_B + (uint32_t)((q+1) & 1)*B_BUF, half, q + 1, tid);
            cp_commit();
            cp_wait1();    // q's buffer complete
        } else {
            cp_wait0();
        }
        __syncthreads();   // q's data visible to all warps

        if (dc == 0) {
            #pragma unroll
            for (int i = 0; i < 2; i++)
                #pragma unroll
                for (int j = 0; j < 8; j++)
                    #pragma unroll
                    for (int v = 0; v < 4; v++) acc[i][j][v] = 0.f;
        }

        const uint32_t bBuf = smem_base + OFF_B + (uint32_t)(q & 1)*B_BUF
                            + (uint32_t)(wc*64)*BSTR_B + bLane;
        #pragma unroll
        for (int ks = 0; ks < 4; ++ks) {
            uint32_t a[2][4];
            uint32_t kb = (uint32_t)(dc*64 + ks*16)*2;
            ldm_x4(a[0], aBase + kb);
            ldm_x4(a[1], aBase + 16*ASTR_B + kb);
            uint32_t bf[4][4];
            uint32_t bAddr = bBuf + (uint32_t)ks*32;
            ldm_x4(bf[0], bAddr);
            ldm_x4(bf[1], bAddr + 16*BSTR_B);
            ldm_x4(bf[2], bAddr + 32*BSTR_B);
            ldm_x4(bf[3], bAddr + 48*BSTR_B);
            #pragma unroll
            for (int i = 0; i < 2; i++) {
                #pragma unroll
                for (int jj = 0; jj < 4; jj++) {
                    mma16816(acc[i][2*jj],   a[i], bf[jj][0], bf[jj][1]);
                    mma16816(acc[i][2*jj+1], a[i], bf[jj][2], bf[jj][3]);
                }
            }
        }

        if (dc == 7) {
            // in-register exp + row reduce over this warp's 64 cols (one class)
            #pragma unroll
            for (int i = 0; i < 2; i++) {
                #pragma unroll
                for (int h = 0; h < 2; h++) {
                    float s = 0.f;
                    #pragma unroll
                    for (int j = 0; j < 8; j++) {
                        s += __expf(2.0f * acc[i][j][h*2 + 0]);
                        s += __expf(2.0f * acc[i][j][h*2 + 1]);
                    }
                    s += __shfl_xor_sync(0xffffffffu, s, 1);
                    s += __shfl_xor_sync(0xffffffffu, s, 2);
                    if ((lane & 3) == 0) {
                        int row = wr*32 + i*16 + h*8 + (lane >> 2);
                        part[row*2 + wc] = s;
                    }
                }
            }
            __syncthreads();
            if (tid < MM) {
                float* dst = g_evi + ((size_t)b*MM + tid)*CC;
                #pragma unroll
                for (int j = 0; j < 2; ++j) {
                    int c = (int)g_clsSorted[half*2048 + nt*128 + j*64];
                    dst[c] = 0.5f * logf(fmaxf(part[tid*2 + j], 1e-8f));
                }
            }
        }
    }
}

// ---------------------------------------------------------------------------
// K3: epilogue per batch (top1, f16 HMMA cosines vs top1 slots, support LSE).
// 256 threads, one block per batch.
// ---------------------------------------------------------------------------
#define KO_S    0u          // S_norm f16 [64][520] = 66560
#define KO_G    66560u      // gathered top1 rows f16 [64][520] = 66560
#define KO_EVI  133120u     // f32 [4096] = 16384
#define KO_SUP  149504u     // f32 [64][68] = 17408
#define KO_W    166912u     // f32 [64]
#define KO_LP   167168u
#define KO_T1V  167424u
#define KO_T1I  167680u     // int [64]
#define KO_SMEM 167936

__global__ void __launch_bounds__(256, 1)
k_out(const float* __restrict__ S_slots,
      const float* __restrict__ alpha,
      float* __restrict__ out) {
    extern __shared__ __align__(1024) char smem[];
    uint32_t smem_base = smem_to_u32(smem);
    float* evi_s = (float*)(smem + KO_EVI);
    float* sup_s = (float*)(smem + KO_SUP);
    float* w_s   = (float*)(smem + KO_W);
    float* lp_s  = (float*)(smem + KO_LP);
    float* t1v   = (float*)(smem + KO_T1V);
    int*   t1i   = (int*)(smem + KO_T1I);

    int b = blockIdx.x, tid = threadIdx.x;
    int wid = tid >> 5, lane = tid & 31;

    for (int i = tid; i < MM*CC; i += 256) evi_s[i] = g_evi[(size_t)b*MM*CC + i];
    if (tid < MM) { w_s[tid] = g_w[b*MM + tid]; lp_s[tid] = g_lp[b*MM + tid]; }

    // normalize S rows -> f16 row-major, stride 520
    {
        const float* sb = S_slots + (size_t)b*MM*DD;
        int row = wid*8;
        for (int rr = 0; rr < 8; rr++, row++) {
            const float4* rp = (const float4*)(sb + (size_t)row*DD);
            float4 v[4]; float ss = 0.f;
            #pragma unroll
            for (int u = 0; u < 4; u++) {
                v[u] = rp[lane + u*32];
                ss += v[u].x*v[u].x + v[u].y*v[u].y + v[u].z*v[u].z + v[u].w*v[u].w;
            }
            #pragma unroll
            for (int o = 16; o > 0; o >>= 1) ss += __shfl_xor_sync(0xffffffffu, ss, o);
            float inv = 1.0f / fmaxf(sqrtf(ss), 1e-12f);
            #pragma unroll
            for (int u = 0; u < 4; u++) {
                __half2 h0 = __floats2half2_rn(v[u].x*inv, v[u].y*inv);
                __half2 h1 = __floats2half2_rn(v[u].z*inv, v[u].w*inv);
                uint2 w; w.x = *(uint32_t*)&h0; w.y = *(uint32_t*)&h1;
                *(uint2*)(smem + KO_S + (uint32_t)row*ASTR_B + (uint32_t)(lane + u*32)*8) = w;
            }
        }
    }
    __syncthreads();

    // top1 over slots per class
    if (tid < CC) {
        int c = tid;
        float best = -INFINITY; int bi = 0;
        for (int m = 0; m < MM; m++) {
            float sc = evi_s[m*CC + c] * w_s[m];
            if (sc > best) { best = sc; bi = m; }
        }
        t1v[c] = best; t1i[c] = bi;
    }
    __syncthreads();

    // gather top1 rows: G[c] = S_norm[t1i[c]] (4 threads per row)
    {
        int c = tid >> 2, q4 = tid & 3;
        int src = t1i[c];
        const uint4* sp = (const uint4*)(smem + KO_S + (uint32_t)src*ASTR_B);
        uint4* gp = (uint4*)(smem + KO_G + (uint32_t)c*ASTR_B);
        for (int k = q4; k < 65; k += 4) gp[k] = sp[k];
    }
    __syncthreads();

    // cos GEMM 64x64x512 via HMMA: warps 2(m) x 4(n), warp tile 32m x 16n
    {
        int wr = wid & 1, wc = wid >> 1;
        const uint32_t aBase = smem_base + KO_S
            + (uint32_t)(wr*32 + (lane & 15))*ASTR_B + (uint32_t)(lane >> 4)*16;
        const uint32_t bBase = smem_base + KO_G
            + (uint32_t)(wc*16 + (lane & 7) + ((lane >> 4) << 3))*ASTR_B
            + (uint32_t)((lane >> 3) & 1)*16;
        float acc[2][2][4];
        #pragma unroll
        for (int i = 0; i < 2; i++)
            #pragma unroll
            for (int j = 0; j < 2; j++)
                #pragma unroll
                for (int v = 0; v < 4; v++) acc[i][j][v] = 0.f;
        #pragma unroll 4
        for (int ks = 0; ks < 32; ++ks) {
            uint32_t kb = (uint32_t)ks*32;
            uint32_t a0[4], a1[4], bf[4];
            ldm_x4(a0, aBase + kb);
            ldm_x4(a1, aBase + 16*ASTR_B + kb);
            ldm_x4(bf, bBase + kb);
            mma16816(acc[0][0], a0, bf[0], bf[1]);
            mma16816(acc[0][1], a0, bf[2], bf[3]);
            mma16816(acc[1][0], a1, bf[0], bf[1]);
            mma16816(acc[1][1], a1, bf[2], bf[3]);
        }
        // write support_raw
        #pragma unroll
        for (int i = 0; i < 2; i++) {
            #pragma unroll
            for (int jj = 0; jj < 2; jj++) {
                int m0 = wr*32 + i*16 + (lane >> 2);
                int c0 = wc*16 + jj*8 + (lane & 3)*2;
                #pragma unroll
                for (int v = 0; v < 4; v++) {
                    int m = m0 + (v >> 1)*8;
                    int c = c0 + (v & 1);
                    float cosv = fmaxf(acc[i][jj][v], 0.f);
                    float sr = evi_s[m*CC + c] + lp_s[m] - cosv;
                    if (m == t1i[c]) sr = -10000.0f;
                    sup_s[m*68 + c] = sr;
                }
            }
        }
    }
    __syncthreads();

    if (tid < CC) {
        int c = tid;
        float mx = -INFINITY;
        for (int m = 0; m < MM; m++) mx = fmaxf(mx, sup_s[m*68 + c]);
        float sum = 0.f;
        for (int m = 0; m < MM; m++) sum += expf(sup_s[m*68 + c] - mx);
        float sval = mx + logf(sum);
        out[b*CC + c] = alpha[0] * (t1v[c] + 0.4f * sval);
    }
}

// ---------------------------------------------------------------------------
extern "C" void kernel_launch(void* const* d_in, const int* in_sizes, int n_in,
                              void* d_out, int out_size) {
    const float* feats     = (const float*)d_in[0];
    const float* slot_prob = (const float*)d_in[1];
    const float* slot_mask = (const float*)d_in[2];
    const float* S_slots   = (const float*)d_in[3];
    const float* Cmat      = (const float*)d_in[4];
    const int*   Ccls      = (const int*)d_in[5];
    const float* alpha     = (const float*)d_in[6];
    float* out = (float*)d_out;

    cudaFuncSetAttribute(k_evi, cudaFuncAttributeMaxDynamicSharedMemorySize, SMEM_EVI);
    cudaFuncSetAttribute(k_out, cudaFuncAttributeMaxDynamicSharedMemorySize, KO_SMEM);

    k_weights<<<BB, MM>>>(slot_prob, slot_mask);
    k_perm<<<KK/256, 256>>>(Ccls);
    prep_C<<<KK*DD/1024, 256>>>(Cmat);
    k_evi<<<2*BB, THREADS, SMEM_EVI>>>(feats);
    k_out<<<BB, 256, KO_SMEM>>>(S_slots, alpha, out);
}

// round 11
// speedup vs baseline: 1.2674x; 1.1277x over previous
#include <cuda_runtime.h>
#include <cuda_fp16.h>
#include <math.h>
#include <stdint.h>

#define BB 128
#define MM 64
#define DD 512
#define KK 4096
#define CC 64

// ---------------------------------------------------------------------------
// scratch (__device__ globals per allocation-free rule)
// ---------------------------------------------------------------------------
__device__ __align__(16) __half g_Ch[KK*DD];      // C, f16, class-sorted rows
__device__ int     g_rank[KK];
__device__ uint8_t g_clsSorted[KK];
__device__ float   g_evi[BB*MM*CC];

// ---------------------------------------------------------------------------
__device__ __forceinline__ uint32_t smem_to_u32(const void* p) {
    uint32_t a;
    asm("{ .reg .u64 t; cvta.to.shared.u64 t, %1; cvt.u32.u64 %0, t; }" : "=r"(a) : "l"(p));
    return a;
}
__device__ __forceinline__ void cp16(uint32_t dst, const void* src) {
    asm volatile("cp.async.cg.shared.global [%0], [%1], 16;" :: "r"(dst), "l"(src));
}
__device__ __forceinline__ void cp_commit() { asm volatile("cp.async.commit_group;" ::: "memory"); }
__device__ __forceinline__ void cp_wait0()  { asm volatile("cp.async.wait_group 0;" ::: "memory"); }
__device__ __forceinline__ void cp_wait1()  { asm volatile("cp.async.wait_group 1;" ::: "memory"); }

__device__ __forceinline__ void ldm_x4(uint32_t r[4], uint32_t addr) {
    asm volatile("ldmatrix.sync.aligned.m8n8.x4.shared.b16 {%0,%1,%2,%3}, [%4];"
        : "=r"(r[0]), "=r"(r[1]), "=r"(r[2]), "=r"(r[3]) : "r"(addr));
}
__device__ __forceinline__ void mma16816(float* c, const uint32_t* a, uint32_t b0, uint32_t b1) {
    asm volatile(
        "mma.sync.aligned.m16n8k16.row.col.f32.f16.f16.f32 "
        "{%0,%1,%2,%3}, {%4,%5,%6,%7}, {%8,%9}, {%0,%1,%2,%3};"
        : "+f"(c[0]), "+f"(c[1]), "+f"(c[2]), "+f"(c[3])
        : "r"(a[0]), "r"(a[1]), "r"(a[2]), "r"(a[3]), "r"(b0), "r"(b1));
}

// ---------------------------------------------------------------------------
// k_perm: deterministic stable class-sort ranks (grid 16, block 256)
// ---------------------------------------------------------------------------
__global__ void k_perm(const int* __restrict__ Ccls) {
    __shared__ int cls_s[KK];
    int tid = threadIdx.x;
    for (int i = tid; i < KK; i += 256) cls_s[i] = Ccls[i] & 63;
    __syncthreads();
    int i = blockIdx.x * 256 + tid;
    int ci = cls_s[i];
    int rank = 0;
    for (int j = 0; j < KK; j++) {
        int cj = cls_s[j];
        rank += (cj < ci) || (cj == ci && j < i);
    }
    g_rank[i] = rank;
    g_clsSorted[rank] = (uint8_t)ci;
}

// prep_C: fp32 -> f16, scatter rows to class-sorted positions
__global__ void prep_C(const float* __restrict__ Cmat) {
    long i = (long)blockIdx.x * 256 + threadIdx.x;      // over float4s
    int row = (int)(i >> 7), col4 = (int)(i & 127);
    float4 v = ((const float4*)Cmat)[i];
    int r = g_rank[row];
    __half2 h0 = __floats2half2_rn(v.x, v.y);
    __half2 h1 = __floats2half2_rn(v.z, v.w);
    uint2 u; u.x = *(uint32_t*)&h0; u.y = *(uint32_t*)&h1;
    ((uint2*)(g_Ch + (size_t)r * DD))[col4] = u;
}

// ---------------------------------------------------------------------------
// K2: f16 HMMA GEMM + in-register class exp-sum. 128 threads, 2 CTAs/SM.
// CTA = (batch b = bx>>1, proto-half = bx&1).
// A (64x512 f16, normalized in-kernel) resident.
// B: 2048 protos as 16 tiles of 128 protos x 8 chunks of 64 k.
// Warps 1(m) x 4(n); warp tile 64m x 32n. Each warp cp.asyncs ONLY its own
// 32 B-rows (exclusive), per-thread wait_group + syncwarp -> NO CTA barrier
// in the q loop; one barrier per tile at the class-combine epilogue.
// ---------------------------------------------------------------------------
#define THREADS 128
#define ASTR_B  1040u       // A row stride bytes (520 f16)
#define BSTR_B  144u        // B row stride bytes (72 f16)
#define OFF_A   0u          // 64 rows x 1040 = 66560
#define OFF_B   66560u      // 4 warps x 2 stages x 4608 = 36864
#define W_BUF   9216u       // per-warp region (2 stages)
#define B_STG   4608u       // 32 rows x 144
#define OFF_PART 103424u    // [2][64][4] f32 = 2048
#define SMEM_EVI 105472

// per-warp exclusive chunk load: 32 rows x 64 k = 4 KB = 8 cp16/lane
__device__ __forceinline__ void load_Bwarp(uint32_t base, int half, int q,
                                           int wid, int lane) {
    const int nt = q >> 3, dc = q & 7;
    const __half* src0 = g_Ch + (size_t)(half*2048 + nt*128 + wid*32)*DD + dc*64;
    int n0 = lane >> 3, g = lane & 7;
    #pragma unroll
    for (int ii = 0; ii < 8; ii++) {
        int n = n0 + ii*4;
        cp16(base + (uint32_t)n*BSTR_B + (uint32_t)g*16, src0 + (size_t)n*DD + g*8);
    }
}

__global__ void __launch_bounds__(THREADS, 2)
k_evi(const float* __restrict__ feats) {
    extern __shared__ __align__(1024) char smem[];
    uint32_t smem_base = smem_to_u32(smem);
    const int tid = threadIdx.x, wid = tid >> 5, lane = tid & 31;
    const int b = blockIdx.x >> 1, half = blockIdx.x & 1;

    float* part = (float*)(smem + OFF_PART);   // [2][64][4]

    const uint32_t wB = smem_base + OFF_B + (uint32_t)wid*W_BUF;

    // start this warp's B chunk 0
    load_Bwarp(wB, half, 0, wid, lane);
    cp_commit();

    // A fill: normalize 64 rows of feats (fp32) -> f16 smem, stride 520
    {
        const float* fb = feats + (size_t)b*MM*DD;
        for (int rr = 0; rr < 16; rr++) {
            int row = wid*16 + rr;
            const float4* rp = (const float4*)(fb + (size_t)row*DD);
            float4 v[4]; float ss = 0.f;
            #pragma unroll
            for (int u = 0; u < 4; u++) {
                v[u] = rp[lane + u*32];
                ss += v[u].x*v[u].x + v[u].y*v[u].y + v[u].z*v[u].z + v[u].w*v[u].w;
            }
            #pragma unroll
            for (int o = 16; o > 0; o >>= 1) ss += __shfl_xor_sync(0xffffffffu, ss, o);
            float inv = 1.0f / fmaxf(sqrtf(ss), 1e-12f);
            #pragma unroll
            for (int u = 0; u < 4; u++) {
                __half2 h0 = __floats2half2_rn(v[u].x*inv, v[u].y*inv);
                __half2 h1 = __floats2half2_rn(v[u].z*inv, v[u].w*inv);
                uint2 w; w.x = *(uint32_t*)&h0; w.y = *(uint32_t*)&h1;
                *(uint2*)(smem + OFF_A + (uint32_t)row*ASTR_B + (uint32_t)(lane + u*32)*8) = w;
            }
        }
    }
    __syncthreads();    // A visible to all warps

    const uint32_t aBase = smem_base + OFF_A
        + (uint32_t)(lane & 15)*ASTR_B + (uint32_t)(lane >> 4)*16;
    const uint32_t bLane = (uint32_t)((lane & 7) + ((lane >> 4) << 3))*BSTR_B
        + (uint32_t)((lane >> 3) & 1)*16;

    float acc[4][4][4];

    for (int q = 0; q < 128; ++q) {
        const int nt = q >> 3, dc = q & 7;

        if (q + 1 < 128) {
            load_Bwarp(wB + (uint32_t)((q+1) & 1)*B_STG, half, q + 1, wid, lane);
            cp_commit();
            cp_wait1();
        } else {
            cp_wait0();
        }
        __syncwarp();

        if (dc == 0) {
            #pragma unroll
            for (int i = 0; i < 4; i++)
                #pragma unroll
                for (int j = 0; j < 4; j++)
                    #pragma unroll
                    for (int v = 0; v < 4; v++) acc[i][j][v] = 0.f;
        }

        const uint32_t bBuf = wB + (uint32_t)(q & 1)*B_STG + bLane;
        #pragma unroll
        for (int ks = 0; ks < 4; ++ks) {
            uint32_t a[4][4];
            uint32_t kb = (uint32_t)(dc*64 + ks*16)*2;
            ldm_x4(a[0], aBase + kb);
            ldm_x4(a[1], aBase + 16*ASTR_B + kb);
            ldm_x4(a[2], aBase + 32*ASTR_B + kb);
            ldm_x4(a[3], aBase + 48*ASTR_B + kb);
            uint32_t bf[2][4];
            uint32_t bAddr = bBuf + (uint32_t)ks*32;
            ldm_x4(bf[0], bAddr);
            ldm_x4(bf[1], bAddr + 16*BSTR_B);
            #pragma unroll
            for (int i = 0; i < 4; i++) {
                mma16816(acc[i][0], a[i], bf[0][0], bf[0][1]);
                mma16816(acc[i][1], a[i], bf[0][2], bf[0][3]);
                mma16816(acc[i][2], a[i], bf[1][0], bf[1][1]);
                mma16816(acc[i][3], a[i], bf[1][2], bf[1][3]);
            }
        }

        if (dc == 7) {
            // exp + row-sum over this warp's 32 protos (half a class)
            float* pb = part + (nt & 1)*64*4;
            #pragma unroll
            for (int i = 0; i < 4; i++) {
                #pragma unroll
                for (int h = 0; h < 2; h++) {
                    float s = 0.f;
                    #pragma unroll
                    for (int j = 0; j < 4; j++) {
                        s += __expf(2.0f * acc[i][j][h*2 + 0]);
                        s += __expf(2.0f * acc[i][j][h*2 + 1]);
                    }
                    s += __shfl_xor_sync(0xffffffffu, s, 1);
                    s += __shfl_xor_sync(0xffffffffu, s, 2);
                    if ((lane & 3) == 0) {
                        int row = i*16 + h*8 + (lane >> 2);
                        pb[row*4 + wid] = s;
                    }
                }
            }
            __syncthreads();   // aligns warps once per tile; part visible
            if (tid < MM) {
                float s0 = pb[tid*4 + 0] + pb[tid*4 + 1];
                float s1 = pb[tid*4 + 2] + pb[tid*4 + 3];
                int c0 = (int)g_clsSorted[half*2048 + nt*128];
                int c1 = (int)g_clsSorted[half*2048 + nt*128 + 64];
                float* dst = g_evi + ((size_t)b*MM + tid)*CC;
                dst[c0] = 0.5f * logf(fmaxf(s0, 1e-8f));
                dst[c1] = 0.5f * logf(fmaxf(s1, 1e-8f));
            }
        }
    }
}

// ---------------------------------------------------------------------------
// K3: fused epilogue per batch: soft-topk weights + log(P_sup), top1,
// f16 HMMA cosines vs top1 slots, support LSE. 256 threads, one block/batch.
// ---------------------------------------------------------------------------
#define KO_S    0u          // S_norm f16 [64][520] = 66560
#define KO_G    66560u      // gathered top1 rows f16 [64][520] = 66560
#define KO_EVI  133120u     // f32 [4096] = 16384
#define KO_SUP  149504u     // f32 [64][68] = 17408
#define KO_W    166912u     // f32 [64]
#define KO_LP   167168u
#define KO_T1V  167424u
#define KO_T1I  167680u     // int [64]
#define KO_SV   167936u     // f32 [64]
#define KO_RED  168192u     // f32 [64]
#define KO_SC   168448u     // f32 [8] scalars
#define KO_SMEM 168480

__global__ void __launch_bounds__(256, 1)
k_out(const float* __restrict__ S_slots,
      const float* __restrict__ slot_prob,
      const float* __restrict__ slot_mask,
      const float* __restrict__ alpha,
      float* __restrict__ out) {
    extern __shared__ __align__(1024) char smem[];
    uint32_t smem_base = smem_to_u32(smem);
    float* evi_s = (float*)(smem + KO_EVI);
    float* sup_s = (float*)(smem + KO_SUP);
    float* w_s   = (float*)(smem + KO_W);
    float* lp_s  = (float*)(smem + KO_LP);
    float* t1v   = (float*)(smem + KO_T1V);
    int*   t1i   = (int*)(smem + KO_T1I);
    float* sv    = (float*)(smem + KO_SV);
    float* red   = (float*)(smem + KO_RED);
    float* sc    = (float*)(smem + KO_SC);   // [0]=mean [1]=zmax [2]=zsum [3]=wsum [4]=tmax [5]=tsum
    int*   topi  = (int*)(smem + KO_SC + 24);

    int b = blockIdx.x, tid = threadIdx.x;
    int wid = tid >> 5, lane = tid & 31;
    int m = tid & 63;    // duplicated x4; all dup writes carry identical values

    // ---- soft-topk weights + log(P_sup) (fused k_weights) ----
    float mask = slot_mask[m];
    float pv = slot_prob[b*MM + m] * mask;
    sv[m] = pv;
    __syncthreads();
    if (tid == 0) {
        for (int t = 0; t < 3; t++) {
            float best = -INFINITY; int bi = 0;
            for (int i = 0; i < MM; i++) if (sv[i] > best) { best = sv[i]; bi = i; }
            topi[t] = bi; sv[bi] = -INFINITY;
        }
    }
    __syncthreads();
    float keep = (m == topi[0] || m == topi[1] || m == topi[2]) ? 1.f : 0.f;
    float q = pv * keep;
    red[m] = q; __syncthreads();
    if (tid == 0) { float s = 0.f; for (int i = 0; i < MM; i++) s += red[i]; sc[0] = s / (float)MM; }
    __syncthreads();
    float z = (q - sc[0]) * 2.0f;
    red[m] = z; __syncthreads();
    if (tid == 0) { float mx = -INFINITY; for (int i = 0; i < MM; i++) mx = fmaxf(mx, red[i]); sc[1] = mx; }
    __syncthreads();
    float e = expf(z - sc[1]);
    red[m] = e; __syncthreads();
    if (tid == 0) { float s = 0.f; for (int i = 0; i < MM; i++) s += red[i]; sc[2] = s; }
    __syncthreads();
    float w = (e / sc[2]) * mask;
    red[m] = w; __syncthreads();
    if (tid == 0) { float s = 0.f; for (int i = 0; i < MM; i++) s += red[i]; sc[3] = s; }
    __syncthreads();
    w = w / fmaxf(sc[3], 1e-8f);
    w_s[m] = w;
    float t = logf(w + 1e-8f) * (1.0f/1.6f);
    red[m] = t; __syncthreads();
    if (tid == 0) { float mx = -INFINITY; for (int i = 0; i < MM; i++) mx = fmaxf(mx, red[i]); sc[4] = mx; }
    __syncthreads();
    float et = expf(t - sc[4]);
    red[m] = et; __syncthreads();
    if (tid == 0) { float s = 0.f; for (int i = 0; i < MM; i++) s += red[i]; sc[5] = s; }
    __syncthreads();
    lp_s[m] = fmaxf(t - sc[4] - logf(sc[5]), -18.420680744f);

    // ---- load evi; normalize S rows -> f16 ----
    for (int i = tid; i < MM*CC; i += 256) evi_s[i] = g_evi[(size_t)b*MM*CC + i];
    {
        const float* sb = S_slots + (size_t)b*MM*DD;
        int row = wid*8;
        for (int rr = 0; rr < 8; rr++, row++) {
            const float4* rp = (const float4*)(sb + (size_t)row*DD);
            float4 v[4]; float ss = 0.f;
            #pragma unroll
            for (int u = 0; u < 4; u++) {
                v[u] = rp[lane + u*32];
                ss += v[u].x*v[u].x + v[u].y*v[u].y + v[u].z*v[u].z + v[u].w*v[u].w;
            }
            #pragma unroll
            for (int o = 16; o > 0; o >>= 1) ss += __shfl_xor_sync(0xffffffffu, ss, o);
            float inv = 1.0f / fmaxf(sqrtf(ss), 1e-12f);
            #pragma unroll
            for (int u = 0; u < 4; u++) {
                __half2 h0 = __floats2half2_rn(v[u].x*inv, v[u].y*inv);
                __half2 h1 = __floats2half2_rn(v[u].z*inv, v[u].w*inv);
                uint2 wv; wv.x = *(uint32_t*)&h0; wv.y = *(uint32_t*)&h1;
                *(uint2*)(smem + KO_S + (uint32_t)row*ASTR_B + (uint32_t)(lane + u*32)*8) = wv;
            }
        }
    }
    __syncthreads();

    // top1 over slots per class
    if (tid < CC) {
        int c = tid;
        float best = -INFINITY; int bi = 0;
        for (int mm = 0; mm < MM; mm++) {
            float scv = evi_s[mm*CC + c] * w_s[mm];
            if (scv > best) { best = scv; bi = mm; }
        }
        t1v[c] = best; t1i[c] = bi;
    }
    __syncthreads();

    // gather top1 rows: G[c] = S_norm[t1i[c]]
    {
        int c = tid >> 2, q4 = tid & 3;
        int src = t1i[c];
        const uint4* sp = (const uint4*)(smem + KO_S + (uint32_t)src*ASTR_B);
        uint4* gp = (uint4*)(smem + KO_G + (uint32_t)c*ASTR_B);
        for (int k = q4; k < 65; k += 4) gp[k] = sp[k];
    }
    __syncthreads();

    // cos GEMM 64x64x512 via HMMA: warps 2(m) x 4(n), warp tile 32m x 16n
    {
        int wr = wid & 1, wc = wid >> 1;
        const uint32_t aBase = smem_base + KO_S
            + (uint32_t)(wr*32 + (lane & 15))*ASTR_B + (uint32_t)(lane >> 4)*16;
        const uint32_t bBase = smem_base + KO_G
            + (uint32_t)(wc*16 + (lane & 7) + ((lane >> 4) << 3))*ASTR_B
            + (uint32_t)((lane >> 3) & 1)*16;
        float acc[2][2][4];
        #pragma unroll
        for (int i = 0; i < 2; i++)
            #pragma unroll
            for (int j = 0; j < 2; j++)
                #pragma unroll
                for (int v = 0; v < 4; v++) acc[i][j][v] = 0.f;
        #pragma unroll 4
        for (int ks = 0; ks < 32; ++ks) {
            uint32_t kb = (uint32_t)ks*32;
            uint32_t a0[4], a1[4], bf[4];
            ldm_x4(a0, aBase + kb);
            ldm_x4(a1, aBase + 16*ASTR_B + kb);
            ldm_x4(bf, bBase + kb);
            mma16816(acc[0][0], a0, bf[0], bf[1]);
            mma16816(acc[0][1], a0, bf[2], bf[3]);
            mma16816(acc[1][0], a1, bf[0], bf[1]);
            mma16816(acc[1][1], a1, bf[2], bf[3]);
        }
        #pragma unroll
        for (int i = 0; i < 2; i++) {
            #pragma unroll
            for (int jj = 0; jj < 2; jj++) {
                int m0 = wr*32 + i*16 + (lane >> 2);
                int c0 = wc*16 + jj*8 + (lane & 3)*2;
                #pragma unroll
                for (int v = 0; v < 4; v++) {
                    int mm = m0 + (v >> 1)*8;
                    int c = c0 + (v & 1);
                    float cosv = fmaxf(acc[i][jj][v], 0.f);
                    float sr = evi_s[mm*CC + c] + lp_s[mm] - cosv;
                    if (mm == t1i[c]) sr = -10000.0f;
                    sup_s[mm*68 + c] = sr;
                }
            }
        }
    }
    __syncthreads();

    if (tid < CC) {
        int c = tid;
        float mx = -INFINITY;
        for (int mm = 0; mm < MM; mm++) mx = fmaxf(mx, sup_s[mm*68 + c]);
        float sum = 0.f;
        for (int mm = 0; mm < MM; mm++) sum += expf(sup_s[mm*68 + c] - mx);
        float sval = mx + logf(sum);
        out[b*CC + c] = alpha[0] * (t1v[c] + 0.4f * sval);
    }
}

// ---------------------------------------------------------------------------
extern "C" void kernel_launch(void* const* d_in, const int* in_sizes, int n_in,
                              void* d_out, int out_size) {
    const float* feats     = (const float*)d_in[0];
    const float* slot_prob = (const float*)d_in[1];
    const float* slot_mask = (const float*)d_in[2];
    const float* S_slots   = (const float*)d_in[3];
    const float* Cmat      = (const float*)d_in[4];
    const int*   Ccls      = (const int*)d_in[5];
    const float* alpha     = (const float*)d_in[6];
    float* out = (float*)d_out;

    cudaFuncSetAttribute(k_evi, cudaFuncAttributeMaxDynamicSharedMemorySize, SMEM_EVI);
    cudaFuncSetAttribute(k_out, cudaFuncAttributeMaxDynamicSharedMemorySize, KO_SMEM);

    k_perm<<<KK/256, 256>>>(Ccls);
    prep_C<<<KK*DD/1024, 256>>>(Cmat);
    k_evi<<<2*BB, THREADS, SMEM_EVI>>>(feats);
    k_out<<<BB, 256, KO_SMEM>>>(S_slots, slot_prob, slot_mask, alpha, out);
}

// round 12
// speedup vs baseline: 1.3648x; 1.0768x over previous
#include <cuda_runtime.h>
#include <cuda_fp16.h>
#include <math.h>
#include <stdint.h>

#define BB 128
#define MM 64
#define DD 512
#define KK 4096
#define CC 64

// ---------------------------------------------------------------------------
// scratch (__device__ globals per allocation-free rule)
// ---------------------------------------------------------------------------
__device__ __align__(16) __half g_Ch[KK*DD];      // C, f16, class-sorted rows
__device__ int     g_rank[KK];
__device__ uint8_t g_clsSorted[KK];
__device__ float   g_evi[BB*MM*CC];

// ---------------------------------------------------------------------------
__device__ __forceinline__ uint32_t smem_to_u32(const void* p) {
    uint32_t a;
    asm("{ .reg .u64 t; cvta.to.shared.u64 t, %1; cvt.u32.u64 %0, t; }" : "=r"(a) : "l"(p));
    return a;
}
__device__ __forceinline__ void cp16(uint32_t dst, const void* src) {
    asm volatile("cp.async.cg.shared.global [%0], [%1], 16;" :: "r"(dst), "l"(src));
}
__device__ __forceinline__ void cp_commit() { asm volatile("cp.async.commit_group;" ::: "memory"); }
__device__ __forceinline__ void cp_wait0()  { asm volatile("cp.async.wait_group 0;" ::: "memory"); }
__device__ __forceinline__ void cp_wait1()  { asm volatile("cp.async.wait_group 1;" ::: "memory"); }

__device__ __forceinline__ void ldm_x4(uint32_t r[4], uint32_t addr) {
    asm volatile("ldmatrix.sync.aligned.m8n8.x4.shared.b16 {%0,%1,%2,%3}, [%4];"
        : "=r"(r[0]), "=r"(r[1]), "=r"(r[2]), "=r"(r[3]) : "r"(addr));
}
__device__ __forceinline__ void mma16816(float* c, const uint32_t* a, uint32_t b0, uint32_t b1) {
    asm volatile(
        "mma.sync.aligned.m16n8k16.row.col.f32.f16.f16.f32 "
        "{%0,%1,%2,%3}, {%4,%5,%6,%7}, {%8,%9}, {%0,%1,%2,%3};"
        : "+f"(c[0]), "+f"(c[1]), "+f"(c[2]), "+f"(c[3])
        : "r"(a[0]), "r"(a[1]), "r"(a[2]), "r"(a[3]), "r"(b0), "r"(b1));
}

// ---------------------------------------------------------------------------
// k_perm: deterministic stable class-sort ranks (grid 64, block 256, 4-way)
// ---------------------------------------------------------------------------
__global__ void k_perm(const int* __restrict__ Ccls) {
    __shared__ int cls_s[KK];
    __shared__ int partial[64][4];
    int tid = threadIdx.x;
    for (int i = tid; i < KK; i += 256) cls_s[i] = Ccls[i] & 63;
    __syncthreads();
    int li = tid >> 2, qt = tid & 3;
    int i = blockIdx.x * 64 + li;
    int ci = cls_s[i];
    int cnt = 0;
    for (int j = qt*1024; j < qt*1024 + 1024; j++) {
        int cj = cls_s[j];
        cnt += (cj < ci) || (cj == ci && j < i);
    }
    partial[li][qt] = cnt;
    __syncthreads();
    if (qt == 0) {
        int rank = partial[li][0] + partial[li][1] + partial[li][2] + partial[li][3];
        g_rank[i] = rank;
        g_clsSorted[rank] = (uint8_t)ci;
    }
}

// prep_C: fp32 -> f16, scatter rows to class-sorted positions
__global__ void prep_C(const float* __restrict__ Cmat) {
    long i = (long)blockIdx.x * 256 + threadIdx.x;      // over float4s
    int row = (int)(i >> 7), col4 = (int)(i & 127);
    float4 v = ((const float4*)Cmat)[i];
    int r = g_rank[row];
    __half2 h0 = __floats2half2_rn(v.x, v.y);
    __half2 h1 = __floats2half2_rn(v.z, v.w);
    uint2 u; u.x = *(uint32_t*)&h0; u.y = *(uint32_t*)&h1;
    ((uint2*)(g_Ch + (size_t)r * DD))[col4] = u;
}

// ---------------------------------------------------------------------------
// K2: f16 HMMA GEMM + class exp-sum. 256 threads (8 warps), 1 CTA/SM.
// CTA = (batch-pair bp = bx>>1, proto-half = bx&1).
// A (128x512 f16, 2 batches, normalized in-kernel) resident.
// B: 2048 protos as 8 tiles of 256 x 16 chunks of 32 k.
// Warps 1(m) x 8(n); warp tile 128m x 32n. Each warp cp.asyncs ONLY its own
// 32 B-rows (exclusive, private double buffer) -> no CTA barrier in the
// chunk loop; ONE barrier per 256-proto tile for the class combine.
// ---------------------------------------------------------------------------
#define THREADS 256
#define ASTR_B  1040u       // A row stride bytes (520 f16)
#define BSTR_B  80u         // B row stride bytes (40 f16, 32k chunk)
#define OFF_A   0u          // 128 x 1040 = 133120
#define OFF_B   133120u     // 8 warps x 2 stages x 2560 = 40960
#define W_BUF   5120u
#define B_STG   2560u       // 32 rows x 80
#define OFF_PART 174080u    // 2 x 128 x 8 f32 = 8192
#define SMEM_EVI 182272

// chunk q: nt = q>>4 (256-proto tile), dc = q&15 (32-k chunk)
// per-warp exclusive: 32 rows x 32 k = 2 KB = 4 cp16/lane
__device__ __forceinline__ void load_Bwarp(uint32_t base, int half, int q,
                                           int wid, int lane) {
    const int nt = q >> 4, dc = q & 15;
    const __half* src0 = g_Ch + (size_t)(half*2048 + nt*256 + wid*32)*DD + dc*32;
    int n0 = lane >> 2, g = lane & 3;
    #pragma unroll
    for (int ii = 0; ii < 4; ii++) {
        int n = n0 + ii*8;
        cp16(base + (uint32_t)n*BSTR_B + (uint32_t)g*16, src0 + (size_t)n*DD + g*8);
    }
}

__global__ void __launch_bounds__(THREADS, 1)
k_evi(const float* __restrict__ feats) {
    extern __shared__ __align__(1024) char smem[];
    uint32_t smem_base = smem_to_u32(smem);
    const int tid = threadIdx.x, wid = tid >> 5, lane = tid & 31;
    const int bp = blockIdx.x >> 1, half = blockIdx.x & 1;

    float* part = (float*)(smem + OFF_PART);   // [2][128][8]

    const uint32_t wB = smem_base + OFF_B + (uint32_t)wid*W_BUF;

    // start this warp's B chunk 0
    load_Bwarp(wB, half, 0, wid, lane);
    cp_commit();

    // A fill: normalize 128 rows (batches 2bp, 2bp+1) fp32 -> f16, stride 520
    {
        const float* fb = feats + (size_t)(bp*2)*MM*DD;
        for (int rr = 0; rr < 16; rr++) {
            int row = wid*16 + rr;
            const float4* rp = (const float4*)(fb + (size_t)row*DD);
            float4 v[4]; float ss = 0.f;
            #pragma unroll
            for (int u = 0; u < 4; u++) {
                v[u] = rp[lane + u*32];
                ss += v[u].x*v[u].x + v[u].y*v[u].y + v[u].z*v[u].z + v[u].w*v[u].w;
            }
            #pragma unroll
            for (int o = 16; o > 0; o >>= 1) ss += __shfl_xor_sync(0xffffffffu, ss, o);
            float inv = 1.0f / fmaxf(sqrtf(ss), 1e-12f);
            #pragma unroll
            for (int u = 0; u < 4; u++) {
                __half2 h0 = __floats2half2_rn(v[u].x*inv, v[u].y*inv);
                __half2 h1 = __floats2half2_rn(v[u].z*inv, v[u].w*inv);
                uint2 w; w.x = *(uint32_t*)&h0; w.y = *(uint32_t*)&h1;
                *(uint2*)(smem + OFF_A + (uint32_t)row*ASTR_B + (uint32_t)(lane + u*32)*8) = w;
            }
        }
    }
    __syncthreads();    // A visible to all warps

    const uint32_t aBase = smem_base + OFF_A
        + (uint32_t)(lane & 15)*ASTR_B + (uint32_t)(lane >> 4)*16;
    const uint32_t bLane = (uint32_t)((lane & 7) + ((lane >> 4) << 3))*BSTR_B
        + (uint32_t)((lane >> 3) & 1)*16;

    float acc[8][4][4];

    #pragma unroll 1
    for (int q = 0; q < 128; ++q) {
        const int nt = q >> 4, dc = q & 15;

        if (q + 1 < 128) {
            load_Bwarp(wB + (uint32_t)((q+1) & 1)*B_STG, half, q + 1, wid, lane);
            cp_commit();
            cp_wait1();
        } else {
            cp_wait0();
        }
        __syncwarp();

        if (dc == 0) {
            #pragma unroll
            for (int i = 0; i < 8; i++)
                #pragma unroll
                for (int j = 0; j < 4; j++)
                    #pragma unroll
                    for (int v = 0; v < 4; v++) acc[i][j][v] = 0.f;
        }

        const uint32_t bBuf = wB + (uint32_t)(q & 1)*B_STG + bLane;
        #pragma unroll
        for (int ks = 0; ks < 2; ++ks) {
            uint32_t kb = (uint32_t)(dc*32 + ks*16)*2;
            uint32_t a[8][4];
            #pragma unroll
            for (int i = 0; i < 8; i++) ldm_x4(a[i], aBase + (uint32_t)(i*16)*ASTR_B + kb);
            uint32_t bf[2][4];
            uint32_t bAddr = bBuf + (uint32_t)ks*32;
            ldm_x4(bf[0], bAddr);
            ldm_x4(bf[1], bAddr + 16*BSTR_B);
            #pragma unroll
            for (int i = 0; i < 8; i++) {
                mma16816(acc[i][0], a[i], bf[0][0], bf[0][1]);
                mma16816(acc[i][1], a[i], bf[0][2], bf[0][3]);
                mma16816(acc[i][2], a[i], bf[1][0], bf[1][1]);
                mma16816(acc[i][3], a[i], bf[1][2], bf[1][3]);
            }
        }

        if (dc == 15) {
            // exp + row-sum over this warp's 32 protos (half a class)
            float* pb = part + (nt & 1)*128*8;
            #pragma unroll
            for (int i = 0; i < 8; i++) {
                #pragma unroll
                for (int h = 0; h < 2; h++) {
                    float s = 0.f;
                    #pragma unroll
                    for (int j = 0; j < 4; j++) {
                        s += __expf(2.0f * acc[i][j][h*2 + 0]);
                        s += __expf(2.0f * acc[i][j][h*2 + 1]);
                    }
                    s += __shfl_xor_sync(0xffffffffu, s, 1);
                    s += __shfl_xor_sync(0xffffffffu, s, 2);
                    if ((lane & 3) == 0) {
                        int row = i*16 + h*8 + (lane >> 2);
                        pb[row*8 + wid] = s;
                    }
                }
            }
            __syncthreads();   // once per 256-proto tile (8 per kernel)
            {
                int row = tid >> 1, cg = tid & 1;    // 2 classes per thread
                int batch = bp*2 + (row >> 6), slot = row & 63;
                float* dst = g_evi + ((size_t)batch*MM + slot)*CC;
                #pragma unroll
                for (int cj = 0; cj < 2; ++cj) {
                    int ci = cg*2 + cj;
                    float s = pb[row*8 + ci*2] + pb[row*8 + ci*2 + 1];
                    int c = (int)g_clsSorted[half*2048 + nt*256 + ci*64];
                    dst[c] = 0.5f * logf(fmaxf(s, 1e-8f));
                }
            }
        }
    }
}

// ---------------------------------------------------------------------------
// K3: fused epilogue per batch (unchanged from R11)
// ---------------------------------------------------------------------------
#define KO_S    0u          // S_norm f16 [64][520] = 66560
#define KO_G    66560u      // gathered top1 rows f16 [64][520] = 66560
#define KO_EVI  133120u     // f32 [4096] = 16384
#define KO_SUP  149504u     // f32 [64][68] = 17408
#define KO_W    166912u     // f32 [64]
#define KO_LP   167168u
#define KO_T1V  167424u
#define KO_T1I  167680u     // int [64]
#define KO_SV   167936u     // f32 [64]
#define KO_RED  168192u     // f32 [64]
#define KO_SC   168448u     // f32 [8] scalars
#define KO_SMEM 168480

__global__ void __launch_bounds__(256, 1)
k_out(const float* __restrict__ S_slots,
      const float* __restrict__ slot_prob,
      const float* __restrict__ slot_mask,
      const float* __restrict__ alpha,
      float* __restrict__ out) {
    extern __shared__ __align__(1024) char smem[];
    uint32_t smem_base = smem_to_u32(smem);
    float* evi_s = (float*)(smem + KO_EVI);
    float* sup_s = (float*)(smem + KO_SUP);
    float* w_s   = (float*)(smem + KO_W);
    float* lp_s  = (float*)(smem + KO_LP);
    float* t1v   = (float*)(smem + KO_T1V);
    int*   t1i   = (int*)(smem + KO_T1I);
    float* sv    = (float*)(smem + KO_SV);
    float* red   = (float*)(smem + KO_RED);
    float* sc    = (float*)(smem + KO_SC);
    int*   topi  = (int*)(smem + KO_SC + 24);

    int b = blockIdx.x, tid = threadIdx.x;
    int wid = tid >> 5, lane = tid & 31;
    int m = tid & 63;

    // ---- soft-topk weights + log(P_sup) ----
    float mask = slot_mask[m];
    float pv = slot_prob[b*MM + m] * mask;
    sv[m] = pv;
    __syncthreads();
    if (tid == 0) {
        for (int t = 0; t < 3; t++) {
            float best = -INFINITY; int bi = 0;
            for (int i = 0; i < MM; i++) if (sv[i] > best) { best = sv[i]; bi = i; }
            topi[t] = bi; sv[bi] = -INFINITY;
        }
    }
    __syncthreads();
    float keep = (m == topi[0] || m == topi[1] || m == topi[2]) ? 1.f : 0.f;
    float q = pv * keep;
    red[m] = q; __syncthreads();
    if (tid == 0) { float s = 0.f; for (int i = 0; i < MM; i++) s += red[i]; sc[0] = s / (float)MM; }
    __syncthreads();
    float z = (q - sc[0]) * 2.0f;
    red[m] = z; __syncthreads();
    if (tid == 0) { float mx = -INFINITY; for (int i = 0; i < MM; i++) mx = fmaxf(mx, red[i]); sc[1] = mx; }
    __syncthreads();
    float e = expf(z - sc[1]);
    red[m] = e; __syncthreads();
    if (tid == 0) { float s = 0.f; for (int i = 0; i < MM; i++) s += red[i]; sc[2] = s; }
    __syncthreads();
    float w = (e / sc[2]) * mask;
    red[m] = w; __syncthreads();
    if (tid == 0) { float s = 0.f; for (int i = 0; i < MM; i++) s += red[i]; sc[3] = s; }
    __syncthreads();
    w = w / fmaxf(sc[3], 1e-8f);
    w_s[m] = w;
    float t = logf(w + 1e-8f) * (1.0f/1.6f);
    red[m] = t; __syncthreads();
    if (tid == 0) { float mx = -INFINITY; for (int i = 0; i < MM; i++) mx = fmaxf(mx, red[i]); sc[4] = mx; }
    __syncthreads();
    float et = expf(t - sc[4]);
    red[m] = et; __syncthreads();
    if (tid == 0) { float s = 0.f; for (int i = 0; i < MM; i++) s += red[i]; sc[5] = s; }
    __syncthreads();
    lp_s[m] = fmaxf(t - sc[4] - logf(sc[5]), -18.420680744f);

    // ---- load evi; normalize S rows -> f16 ----
    for (int i = tid; i < MM*CC; i += 256) evi_s[i] = g_evi[(size_t)b*MM*CC + i];
    {
        const float* sb = S_slots + (size_t)b*MM*DD;
        int row = wid*8;
        for (int rr = 0; rr < 8; rr++, row++) {
            const float4* rp = (const float4*)(sb + (size_t)row*DD);
            float4 v[4]; float ss = 0.f;
            #pragma unroll
            for (int u = 0; u < 4; u++) {
                v[u] = rp[lane + u*32];
                ss += v[u].x*v[u].x + v[u].y*v[u].y + v[u].z*v[u].z + v[u].w*v[u].w;
            }
            #pragma unroll
            for (int o = 16; o > 0; o >>= 1) ss += __shfl_xor_sync(0xffffffffu, ss, o);
            float inv = 1.0f / fmaxf(sqrtf(ss), 1e-12f);
            #pragma unroll
            for (int u = 0; u < 4; u++) {
                __half2 h0 = __floats2half2_rn(v[u].x*inv, v[u].y*inv);
                __half2 h1 = __floats2half2_rn(v[u].z*inv, v[u].w*inv);
                uint2 wv; wv.x = *(uint32_t*)&h0; wv.y = *(uint32_t*)&h1;
                *(uint2*)(smem + KO_S + (uint32_t)row*ASTR_B + (uint32_t)(lane + u*32)*8) = wv;
            }
        }
    }
    __syncthreads();

    if (tid < CC) {
        int c = tid;
        float best = -INFINITY; int bi = 0;
        for (int mm = 0; mm < MM; mm++) {
            float scv = evi_s[mm*CC + c] * w_s[mm];
            if (scv > best) { best = scv; bi = mm; }
        }
        t1v[c] = best; t1i[c] = bi;
    }
    __syncthreads();

    {
        int c = tid >> 2, q4 = tid & 3;
        int src = t1i[c];
        const uint4* sp = (const uint4*)(smem + KO_S + (uint32_t)src*ASTR_B);
        uint4* gp = (uint4*)(smem + KO_G + (uint32_t)c*ASTR_B);
        for (int k = q4; k < 65; k += 4) gp[k] = sp[k];
    }
    __syncthreads();

    {
        int wr = wid & 1, wc = wid >> 1;
        const uint32_t aBase = smem_base + KO_S
            + (uint32_t)(wr*32 + (lane & 15))*ASTR_B + (uint32_t)(lane >> 4)*16;
        const uint32_t bBase = smem_base + KO_G
            + (uint32_t)(wc*16 + (lane & 7) + ((lane >> 4) << 3))*ASTR_B
            + (uint32_t)((lane >> 3) & 1)*16;
        float acc[2][2][4];
        #pragma unroll
        for (int i = 0; i < 2; i++)
            #pragma unroll
            for (int j = 0; j < 2; j++)
                #pragma unroll
                for (int v = 0; v < 4; v++) acc[i][j][v] = 0.f;
        #pragma unroll 4
        for (int ks = 0; ks < 32; ++ks) {
            uint32_t kb = (uint32_t)ks*32;
            uint32_t a0[4], a1[4], bf[4];
            ldm_x4(a0, aBase + kb);
            ldm_x4(a1, aBase + 16*ASTR_B + kb);
            ldm_x4(bf, bBase + kb);
            mma16816(acc[0][0], a0, bf[0], bf[1]);
            mma16816(acc[0][1], a0, bf[2], bf[3]);
            mma16816(acc[1][0], a1, bf[0], bf[1]);
            mma16816(acc[1][1], a1, bf[2], bf[3]);
        }
        #pragma unroll
        for (int i = 0; i < 2; i++) {
            #pragma unroll
            for (int jj = 0; jj < 2; jj++) {
                int m0 = wr*32 + i*16 + (lane >> 2);
                int c0 = wc*16 + jj*8 + (lane & 3)*2;
                #pragma unroll
                for (int v = 0; v < 4; v++) {
                    int mm = m0 + (v >> 1)*8;
                    int c = c0 + (v & 1);
                    float cosv = fmaxf(acc[i][jj][v], 0.f);
                    float sr = evi_s[mm*CC + c] + lp_s[mm] - cosv;
                    if (mm == t1i[c]) sr = -10000.0f;
                    sup_s[mm*68 + c] = sr;
                }
            }
        }
    }
    __syncthreads();

    if (tid < CC) {
        int c = tid;
        float mx = -INFINITY;
        for (int mm = 0; mm < MM; mm++) mx = fmaxf(mx, sup_s[mm*68 + c]);
        float sum = 0.f;
        for (int mm = 0; mm < MM; mm++) sum += expf(sup_s[mm*68 + c] - mx);
        float sval = mx + logf(sum);
        out[b*CC + c] = alpha[0] * (t1v[c] + 0.4f * sval);
    }
}

// ---------------------------------------------------------------------------
extern "C" void kernel_launch(void* const* d_in, const int* in_sizes, int n_in,
                              void* d_out, int out_size) {
    const float* feats     = (const float*)d_in[0];
    const float* slot_prob = (const float*)d_in[1];
    const float* slot_mask = (const float*)d_in[2];
    const float* S_slots   = (const float*)d_in[3];
    const float* Cmat      = (const float*)d_in[4];
    const int*   Ccls      = (const int*)d_in[5];
    const float* alpha     = (const float*)d_in[6];
    float* out = (float*)d_out;

    cudaFuncSetAttribute(k_evi, cudaFuncAttributeMaxDynamicSharedMemorySize, SMEM_EVI);
    cudaFuncSetAttribute(k_out, cudaFuncAttributeMaxDynamicSharedMemorySize, KO_SMEM);

    k_perm<<<KK/64, 256>>>(Ccls);
    prep_C<<<KK*DD/1024, 256>>>(Cmat);
    k_evi<<<BB, THREADS, SMEM_EVI>>>(feats);
    k_out<<<BB, 256, KO_SMEM>>>(S_slots, slot_prob, slot_mask, alpha, out);
}